// round 7
// baseline (speedup 1.0000x reference)
#include <cuda_runtime.h>
#include <math.h>
#include <stdint.h>

// ---------------- device scratch ----------------
__device__ __align__(16) float g_trel[500 * 100];
__device__ __align__(16) float g_tin[8192 * 500];
__device__ __align__(16) float g_xp[8192 * 1024];
__device__ __align__(16) float g_outseq[8192 * 256];

// ---------------- helpers ----------------
__device__ __forceinline__ unsigned smem_u32(const void* p) {
    return (unsigned)__cvta_generic_to_shared(p);
}
__device__ __forceinline__ void cpa16(unsigned dst, const void* src) {
    asm volatile("cp.async.cg.shared.global [%0], [%1], 16;\n" :: "r"(dst), "l"(src));
}
#define CPA_COMMIT() asm volatile("cp.async.commit_group;\n")
template <int N> __device__ __forceinline__ void cpa_wait() {
    asm volatile("cp.async.wait_group %0;\n" :: "n"(N));
}
#define FMA2(acc, h, w) \
    asm("fma.rn.f32x2 %0, %1, %2, %0;" : "+l"(acc) : "l"(h), "l"(w))
#define UNPACK2(lo, hi, src) \
    asm("mov.b64 {%0, %1}, %2;" : "=f"(lo), "=f"(hi) : "l"(src))
#define PACKF2(dst, a, b) \
    asm("mov.b64 %0, {%1, %2};" : "=l"(dst) : "f"(a), "f"(b))
#define CLUSTER_ARRIVE() asm volatile("barrier.cluster.arrive.aligned;" ::: "memory")
#define CLUSTER_WAIT()   asm volatile("barrier.cluster.wait.aligned;" ::: "memory")

#define MBAR_INIT(mb, cnt) \
    asm volatile("mbarrier.init.shared.b64 [%0], %1;" :: "r"(mb), "r"(cnt) : "memory")
#define MBAR_EXPECT_TX(mb, bytes) \
    asm volatile("mbarrier.arrive.expect_tx.shared.b64 _, [%0], %1;" :: "r"(mb), "r"(bytes) : "memory")
#define ST_ASYNC_F32(raddr, vbits, rmbar) \
    asm volatile("st.async.shared::cluster.mbarrier::complete_tx::bytes.b32 [%0], %1, [%2];" \
                 :: "r"(raddr), "r"(vbits), "r"(rmbar) : "memory")

__device__ __forceinline__ void mbar_wait_cluster(unsigned mbar, unsigned parity) {
    asm volatile(
        "{\n\t"
        ".reg .pred P;\n\t"
        "WAITLOOP_%=:\n\t"
        "mbarrier.try_wait.parity.acquire.cluster.shared::cta.b64 P, [%0], %1, 0x989680;\n\t"
        "@P bra.uni WAITDONE_%=;\n\t"
        "bra.uni WAITLOOP_%=;\n\t"
        "WAITDONE_%=:\n\t"
        "}"
        :: "r"(mbar), "r"(parity) : "memory");
}

__device__ __forceinline__ float fast_sigmoid(float x) {
    return __fdividef(1.f, 1.f + __expf(-x));
}
__device__ __forceinline__ float fast_tanh(float x) {
    float e = __expf(2.f * x);
    return 1.f - __fdividef(2.f, e + 1.f);
}

// ============================================================================
// K0: precompute tanh(rel_emb)
// ============================================================================
__global__ void k_tanh_rel(const float* __restrict__ rel) {
    int i = blockIdx.x * 256 + threadIdx.x;
    if (i < 500 * 100) g_trel[i] = tanhf(rel[i]);
}

// ============================================================================
// K1: graph attention. 512 CTAs x 512 threads, 16 tokens per CTA.
// ============================================================================
#define TOK_SW    0
#define TOK_SHT   20400
#define TOK_SRT   33456
#define TOK_SE    39856
#define TOK_SIDX  39888
#define TOK_SVAL  41424
#define TOK_SPART 41440
#define TOK_SMEM  ((41440 + 32 * 52) * 4)

__device__ __forceinline__ void tok_stage(float* sm, int buf, int it,
                                          const float* ent_emb) {
    const int* idx = (const int*)(sm + TOK_SIDX) + it * 96;
    float* sHT = sm + TOK_SHT + buf * 32 * 204;
    float* sRT = sm + TOK_SRT + buf * 32 * 100;
    for (int i = threadIdx.x; i < 2400; i += 512) {
        if (i < 1600) {
            int t = i / 50, j = i - t * 50;
            int ent = (j < 25) ? idx[t * 3] : idx[t * 3 + 1];
            int jj = (j < 25) ? j : (j - 25);
            int dstf = t * 204 + ((j < 25) ? (j * 4) : (100 + jj * 4));
            cpa16(smem_u32(sHT + dstf), ent_emb + (size_t)ent * 100 + jj * 4);
        } else {
            int r = i - 1600;
            int t = r / 25, j = r - t * 25;
            int rl = idx[t * 3 + 2];
            cpa16(smem_u32(sRT + t * 100 + j * 4), g_trel + rl * 100 + j * 4);
        }
    }
}

__global__ void __launch_bounds__(512, 1)
k_token(const int* __restrict__ inputs, const int* __restrict__ triples,
        const int* __restrict__ id2, const float* __restrict__ word_emb,
        const float* __restrict__ ent_emb, const float* __restrict__ W_ent)
{
    extern __shared__ float sm[];
    const int tid = threadIdx.x;
    const int tok0 = blockIdx.x * 16;

    for (int i = tid; i < 384; i += 512)
        cpa16(smem_u32(sm + TOK_SIDX) + i * 16, triples + (size_t)tok0 * 96 + i * 4);
    for (int i = tid; i < 5000; i += 512) {
        int d = i / 50, j = i - d * 50;
        cpa16(smem_u32(sm + TOK_SW + d * 204 + j * 4), W_ent + d * 200 + j * 4);
    }
    CPA_COMMIT();
    cpa_wait<0>();
    __syncthreads();

    {
        int it = tid >> 5, lane = tid & 31;
        int v = id2[(size_t)(tok0 + it) * 32 + lane];
        unsigned m = __ballot_sync(0xffffffffu, v != -1);
        if (lane == 0) ((int*)(sm + TOK_SVAL))[it] = (m != 0u);
    }

    tok_stage(sm, 0, 0, ent_emb);
    CPA_COMMIT();

    const int tt = tid & 7;
    const int dd = tid >> 3;

    for (int it = 0; it < 16; ++it) {
        const int buf = it & 1;
        if (it < 15) {
            tok_stage(sm, buf ^ 1, it + 1, ent_emb);
            CPA_COMMIT();
            cpa_wait<1>();
        } else {
            cpa_wait<0>();
        }
        __syncthreads();

        const float* sHT = sm + TOK_SHT + buf * 32 * 204;
        const float* sRT = sm + TOK_SRT + buf * 32 * 100;

        if (tid < 400) {
            const float* pa = sHT + tt * 204;
            const float* pb0 = sm + TOK_SW + dd * 204;
            const float* pb1 = sm + TOK_SW + (dd + 50) * 204;
            float acc[4][2];
            #pragma unroll
            for (int i = 0; i < 4; i++) { acc[i][0] = 0.f; acc[i][1] = 0.f; }

            #pragma unroll 2
            for (int j = 0; j < 50; ++j) {
                float4 b0 = *(const float4*)(pb0 + j * 4);
                float4 b1 = *(const float4*)(pb1 + j * 4);
                #pragma unroll
                for (int i = 0; i < 4; ++i) {
                    float4 a = *(const float4*)(pa + i * (8 * 204) + j * 4);
                    acc[i][0] = fmaf(a.x, b0.x, fmaf(a.y, b0.y, fmaf(a.z, b0.z, fmaf(a.w, b0.w, acc[i][0]))));
                    acc[i][1] = fmaf(a.x, b1.x, fmaf(a.y, b1.y, fmaf(a.z, b1.z, fmaf(a.w, b1.w, acc[i][1]))));
                }
            }
            #pragma unroll
            for (int i = 0; i < 4; ++i) {
                int t = tt + 8 * i;
                float c = tanhf(acc[i][0]) * sRT[t * 100 + dd]
                        + tanhf(acc[i][1]) * sRT[t * 100 + dd + 50];
                sm[TOK_SPART + t * 52 + dd] = c;
            }
        }
        __syncthreads();

        {
            int t = tid >> 4, l = tid & 15;
            float v = sm[TOK_SPART + t * 52 + l]
                    + sm[TOK_SPART + t * 52 + l + 16]
                    + sm[TOK_SPART + t * 52 + l + 32];
            if (l < 2) v += sm[TOK_SPART + t * 52 + l + 48];
            #pragma unroll
            for (int o = 8; o; o >>= 1) v += __shfl_xor_sync(0xffffffffu, v, o);
            if (l == 0) sm[TOK_SE + t] = v;
        }
        __syncthreads();

        if (tid < 32) {
            float v = sm[TOK_SE + tid];
            float m = v;
            #pragma unroll
            for (int o = 16; o; o >>= 1) m = fmaxf(m, __shfl_xor_sync(0xffffffffu, m, o));
            float e = expf(v - m);
            float z = e;
            #pragma unroll
            for (int o = 16; o; o >>= 1) z += __shfl_xor_sync(0xffffffffu, z, o);
            sm[TOK_SE + tid] = e / z;
        }
        __syncthreads();

        const int token = tok0 + it;
        const int widx = inputs[token];
        const float2* wsrc = (const float2*)(word_emb + (size_t)widx * 300);
        float2* wdst = (float2*)(g_tin + (size_t)token * 500);
        for (int j = tid; j < 150; j += 512) wdst[j] = wsrc[j];
        if (tid < 200) {
            float ge = 0.f;
            #pragma unroll 8
            for (int t = 0; t < 32; ++t) ge += sm[TOK_SE + t] * sHT[t * 204 + tid];
            int valid = ((int*)(sm + TOK_SVAL))[it];
            g_tin[(size_t)token * 500 + 300 + tid] = valid ? ge : 0.f;
        }
        __syncthreads();
    }
}

// ============================================================================
// K2: g_xp[8192,1024] = g_tin[8192,500] @ w_ih^T + (b_ih + b_hh)
// 128x64 tiles, 4m x 8n per thread, packed f32x2 (n-pairs). 256 threads.
// ============================================================================
__global__ void __launch_bounds__(256)
k_gemm_x(const float* __restrict__ wih, const float* __restrict__ bih,
         const float* __restrict__ bhh)
{
    __shared__ float As[16 * 132];   // [k][m], 128 m + pad
    __shared__ float Bs[16 * 68];    // [k][n], 64 n + pad
    const int tid = threadIdx.x;
    const int n0 = blockIdx.x * 64;
    const int m0 = blockIdx.y * 128;
    const int lmA = tid >> 1;            // 0..127
    const int lkA = (tid & 1) * 8;
    const int lmB = tid >> 2;            // 0..63
    const int lkB = (tid & 3) * 4;
    const int ty = tid >> 3;             // 0..31 -> m rows ty*4..+3
    const int tx = tid & 7;              // 0..7  -> n cols tx*8..+7

    unsigned long long acc2[4][4];
    #pragma unroll
    for (int i = 0; i < 4; i++)
        #pragma unroll
        for (int j = 0; j < 4; j++) acc2[i][j] = 0ull;

    const float* arow = g_tin + (size_t)(m0 + lmA) * 500;
    const float* brow = wih   + (size_t)(n0 + lmB) * 500;

    for (int kt = 0; kt < 32; ++kt) {
        int kb = kt * 16;
        #pragma unroll
        for (int j = 0; j < 8; ++j) {
            int k = kb + lkA + j;
            As[(lkA + j) * 132 + lmA] = (k < 500) ? arow[k] : 0.f;
        }
        #pragma unroll
        for (int j = 0; j < 4; ++j) {
            int k = kb + lkB + j;
            Bs[(lkB + j) * 68 + lmB] = (k < 500) ? brow[k] : 0.f;
        }
        __syncthreads();
        #pragma unroll
        for (int k = 0; k < 16; ++k) {
            float4 a = *(const float4*)&As[k * 132 + ty * 4];
            ulonglong2 b01 = *(const ulonglong2*)&Bs[k * 68 + tx * 8];
            ulonglong2 b23 = *(const ulonglong2*)&Bs[k * 68 + tx * 8 + 4];
            unsigned long long s0, s1, s2, s3;
            PACKF2(s0, a.x, a.x); PACKF2(s1, a.y, a.y);
            PACKF2(s2, a.z, a.z); PACKF2(s3, a.w, a.w);
            FMA2(acc2[0][0], b01.x, s0); FMA2(acc2[0][1], b01.y, s0);
            FMA2(acc2[0][2], b23.x, s0); FMA2(acc2[0][3], b23.y, s0);
            FMA2(acc2[1][0], b01.x, s1); FMA2(acc2[1][1], b01.y, s1);
            FMA2(acc2[1][2], b23.x, s1); FMA2(acc2[1][3], b23.y, s1);
            FMA2(acc2[2][0], b01.x, s2); FMA2(acc2[2][1], b01.y, s2);
            FMA2(acc2[2][2], b23.x, s2); FMA2(acc2[2][3], b23.y, s2);
            FMA2(acc2[3][0], b01.x, s3); FMA2(acc2[3][1], b01.y, s3);
            FMA2(acc2[3][2], b23.x, s3); FMA2(acc2[3][3], b23.y, s3);
        }
        __syncthreads();
    }

    float bb[8];
    #pragma unroll
    for (int j = 0; j < 8; ++j) {
        int n = n0 + tx * 8 + j;
        bb[j] = bih[n] + bhh[n];
    }
    #pragma unroll
    for (int i = 0; i < 4; ++i) {
        float4 o0, o1;
        UNPACK2(o0.x, o0.y, acc2[i][0]); UNPACK2(o0.z, o0.w, acc2[i][1]);
        UNPACK2(o1.x, o1.y, acc2[i][2]); UNPACK2(o1.z, o1.w, acc2[i][3]);
        o0.x += bb[0]; o0.y += bb[1]; o0.z += bb[2]; o0.w += bb[3];
        o1.x += bb[4]; o1.y += bb[5]; o1.z += bb[6]; o1.w += bb[7];
        float* orow = g_xp + (size_t)(m0 + ty * 4 + i) * 1024 + n0 + tx * 8;
        *(float4*)orow = o0;
        *(float4*)(orow + 4) = o1;
    }
}

// ============================================================================
// K3: cluster LSTM v4 — mbarrier tx-count exchange (no cluster.sync in loop).
// 16 clusters x 8 CTAs x 256 threads. Weights in regs (4 gates x 32k u64
// pairs). Per step: GEMV (LDS.128 swizzled + FFMA2), butterfly reduce,
// activation (lanes ks<4), st.async h -> all 8 peers completing on the
// peers' step mbarrier (expect_tx = 4096 B = full 4-batch h).
// ============================================================================
__global__ void __launch_bounds__(256, 1) __cluster_dims__(8, 1, 1)
k_lstm(const float* __restrict__ whh, const int* __restrict__ lengths)
{
    __shared__ __align__(16) float sH[2][4][256];   // [buf][batch][k swizzled]
    __shared__ __align__(8) unsigned long long sMbar[2];

    const int tid  = threadIdx.x;
    const int rank = blockIdx.x & 7;
    const int cid  = blockIdx.x >> 3;
    const int b0g  = cid * 4;

    const int hc_l = tid >> 3;          // 0..31
    const int ks   = tid & 7;           // k-slice
    const int k_g  = rank * 32 + hc_l;

    // ---- persistent packed weights: 4 gates x 32 k = 64 u64 = 128 regs ----
    unsigned long long w[4][16];
    #pragma unroll
    for (int g = 0; g < 4; ++g) {
        const float4* p = (const float4*)(whh + ((size_t)(g * 256 + k_g)) * 256 + ks * 32);
        #pragma unroll
        for (int j = 0; j < 8; ++j) {
            float4 v = __ldg(p + j);
            PACKF2(w[g][2*j],   v.x, v.y);
            PACKF2(w[g][2*j+1], v.z, v.w);
        }
    }

    for (int i = tid; i < 2 * 4 * 256; i += 256) (&sH[0][0][0])[i] = 0.f;

    const unsigned mb0 = smem_u32(&sMbar[0]);
    if (tid == 0) {
        MBAR_INIT(mb0, 1);
        MBAR_INIT(mb0 + 8, 1);
        MBAR_EXPECT_TX(mb0, 4096);
        MBAR_EXPECT_TX(mb0 + 8, 4096);
    }

    // precompute remote bases (DSMEM): peer sH base + peer mbar base
    unsigned rH[8], rM[8];
    const unsigned hbase = smem_u32(&sH[0][0][0]);
    #pragma unroll
    for (int rr = 0; rr < 8; ++rr) {
        asm("mapa.shared::cluster.u32 %0, %1, %2;" : "=r"(rH[rr]) : "r"(hbase), "r"(rr));
        asm("mapa.shared::cluster.u32 %0, %1, %2;" : "=r"(rM[rr]) : "r"(mb0),   "r"(rr));
    }

    const int ab = ks;                  // batch for activation lanes (ks<4)
    float cst = 0.f;
    int mylen = 0;
    if (ks < 4) mylen = lengths[b0g + ab];
    const int sw_idx = k_g ^ (rank << 2);

    __syncthreads();
    CLUSTER_ARRIVE(); CLUSTER_WAIT();   // peers' mbarriers armed

    int ph0 = 0, ph1 = 0;
    int buf = 0;
    for (int s = 0; s < 128; ++s) {
        // prefetch x-projection gates (independent of h)
        float xg0 = 0.f, xg1 = 0.f, xg2 = 0.f, xg3 = 0.f;
        if (ks < 4) {
            const float* xp = g_xp + ((size_t)((b0g + ab) * 128 + s)) * 1024 + k_g;
            xg0 = __ldg(xp);       xg1 = __ldg(xp + 256);
            xg2 = __ldg(xp + 512); xg3 = __ldg(xp + 768);
        }

        if (s > 0) {
            unsigned mb = mb0 + 8 * (s & 1);
            int par = (s & 1) ? ph1 : ph0;
            mbar_wait_cluster(mb, (unsigned)par);
            if (s & 1) ph1 ^= 1; else ph0 ^= 1;
            if (tid == 0) MBAR_EXPECT_TX(mb, 4096);   // re-arm for step s+2
        }

        // ---- GEMV: 32 LDS.128 + 256 FMA2 ----
        unsigned long long acc[4][4];
        #pragma unroll
        for (int g = 0; g < 4; ++g)
            #pragma unroll
            for (int b = 0; b < 4; ++b) acc[g][b] = 0ull;

        const float* hb = &sH[buf][0][0];
        #pragma unroll
        for (int i = 0; i < 8; ++i) {
            int off = (ks * 32 + i * 4) ^ (ks << 2);
            ulonglong2 x0 = *(const ulonglong2*)(hb + 0   + off);
            ulonglong2 x1 = *(const ulonglong2*)(hb + 256 + off);
            ulonglong2 x2 = *(const ulonglong2*)(hb + 512 + off);
            ulonglong2 x3 = *(const ulonglong2*)(hb + 768 + off);
            #pragma unroll
            for (int g = 0; g < 4; ++g) {
                FMA2(acc[g][0], x0.x, w[g][2*i]); FMA2(acc[g][0], x0.y, w[g][2*i+1]);
                FMA2(acc[g][1], x1.x, w[g][2*i]); FMA2(acc[g][1], x1.y, w[g][2*i+1]);
                FMA2(acc[g][2], x2.x, w[g][2*i]); FMA2(acc[g][2], x2.y, w[g][2*i+1]);
                FMA2(acc[g][3], x3.x, w[g][2*i]); FMA2(acc[g][3], x3.y, w[g][2*i+1]);
            }
        }

        float r[4][4];
        #pragma unroll
        for (int g = 0; g < 4; ++g)
            #pragma unroll
            for (int b = 0; b < 4; ++b) {
                float lo, hi;
                UNPACK2(lo, hi, acc[g][b]);
                r[g][b] = lo + hi;
            }
        #pragma unroll
        for (int o = 1; o < 8; o <<= 1)
            #pragma unroll
            for (int g = 0; g < 4; ++g)
                #pragma unroll
                for (int b = 0; b < 4; ++b)
                    r[g][b] += __shfl_xor_sync(0xffffffffu, r[g][b], o);

        // all reads of sH[buf] done before any store of this step
        // (also orders tid0's re-arm before our outgoing stores)
        __syncthreads();

        // ---- activation + st.async broadcast (lanes ks<4, batch ab=ks) ----
        if (ks < 4) {
            float gi = xg0 + r[0][ab];
            float gf = xg1 + r[1][ab];
            float gg = xg2 + r[2][ab];
            float go = xg3 + r[3][ab];
            float si = fast_sigmoid(gi);
            float sf = fast_sigmoid(gf);
            float so = fast_sigmoid(go);
            cst = sf * cst + si * fast_tanh(gg);
            float hv = so * fast_tanh(cst);
            g_outseq[((size_t)((b0g + ab) * 128 + s)) * 256 + k_g] =
                (s < mylen) ? hv : 0.f;
            if (s < 127) {
                unsigned hoff = (unsigned)(((buf ^ 1) * 1024 + ab * 256 + sw_idx) * 4);
                unsigned moff = 8u * (unsigned)((s + 1) & 1);
                unsigned vb = __float_as_uint(hv);
                #pragma unroll
                for (int rr = 0; rr < 8; ++rr)
                    ST_ASYNC_F32(rH[rr] + hoff, vb, rM[rr] + moff);
            }
        }
        buf ^= 1;
    }
    CLUSTER_ARRIVE(); CLUSTER_WAIT();
}

// ============================================================================
// K4: attention pool + classifier. out = [ log_probs (64*3) | p (64*128) ]
// ============================================================================
__global__ void __launch_bounds__(256)
k_final(const float* __restrict__ W_att, const float* __restrict__ b_att,
        const float* __restrict__ W_out, const float* __restrict__ b_out,
        float* __restrict__ out)
{
    __shared__ float sLog[128];
    __shared__ float sP[128];
    __shared__ float sEnc[256];
    __shared__ float sZ[3];
    const int tid = threadIdx.x;
    const int b = blockIdx.x;

    if (tid < 128) {
        const float* o = g_outseq + (size_t)(b * 128 + tid) * 256;
        float a = 0.f;
        for (int h = 0; h < 256; ++h) a += o[h] * W_att[h];
        sLog[tid] = a + b_att[0];
    }
    __syncthreads();

    if (tid == 0) {
        float mx = -INFINITY;
        for (int s = 0; s < 128; ++s) {
            float m = (sLog[s] != 0.f) ? 1.f : 0.f;
            mx = fmaxf(mx, sLog[s] * m);
        }
        float den = 0.f;
        for (int s = 0; s < 128; ++s) {
            float m = (sLog[s] != 0.f) ? 1.f : 0.f;
            den += expf(sLog[s] * m - mx);
        }
        float sum2 = 0.f;
        for (int s = 0; s < 128; ++s) {
            float m = (sLog[s] != 0.f) ? 1.f : 0.f;
            float pv = expf(sLog[s] * m - mx) / den * m;
            sP[s] = pv;
            sum2 += pv;
        }
        float inv = 1.f / (sum2 + 1e-13f);
        for (int s = 0; s < 128; ++s) sP[s] *= inv;
    }
    __syncthreads();

    {
        float a = 0.f;
        const float* base = g_outseq + (size_t)b * 128 * 256 + tid;
        for (int s = 0; s < 128; ++s) a += sP[s] * base[s * 256];
        sEnc[tid] = a;
    }
    __syncthreads();

    if (tid < 3) {
        float z = b_out[tid];
        const float* wv = W_out + tid * 256;
        for (int h = 0; h < 256; ++h) z += sEnc[h] * wv[h];
        sZ[tid] = z;
    }
    __syncthreads();
    if (tid < 3) {
        float mx = fmaxf(sZ[0], fmaxf(sZ[1], sZ[2]));
        float lse = mx + logf(expf(sZ[0] - mx) + expf(sZ[1] - mx) + expf(sZ[2] - mx));
        out[b * 3 + tid] = sZ[tid] - lse;
    }
    if (tid < 128) out[192 + b * 128 + tid] = sP[tid];
}

// ============================================================================
extern "C" void kernel_launch(void* const* d_in, const int* in_sizes, int n_in,
                              void* d_out, int out_size)
{
    const int*   inputs   = (const int*)d_in[0];
    const int*   triples  = (const int*)d_in[1];
    const int*   lengths  = (const int*)d_in[2];
    const int*   id2      = (const int*)d_in[3];
    const float* word_emb = (const float*)d_in[4];
    const float* ent_emb  = (const float*)d_in[5];
    const float* rel_emb  = (const float*)d_in[6];
    const float* W_ent    = (const float*)d_in[7];
    const float* w_ih     = (const float*)d_in[8];
    const float* w_hh     = (const float*)d_in[9];
    const float* b_ih     = (const float*)d_in[10];
    const float* b_hh     = (const float*)d_in[11];
    const float* W_att    = (const float*)d_in[12];
    const float* b_att    = (const float*)d_in[13];
    const float* W_out    = (const float*)d_in[14];
    const float* b_out    = (const float*)d_in[15];
    float* out = (float*)d_out;

    cudaFuncSetAttribute(k_token, cudaFuncAttributeMaxDynamicSharedMemorySize, TOK_SMEM);

    k_tanh_rel<<<(50000 + 255) / 256, 256>>>(rel_emb);
    k_token<<<512, 512, TOK_SMEM>>>(inputs, triples, id2, word_emb, ent_emb, W_ent);
    dim3 g2(16, 64);
    k_gemm_x<<<g2, 256>>>(w_ih, b_ih, b_hh);
    k_lstm<<<128, 256>>>(w_hh, lengths);
    k_final<<<64, 256>>>(W_att, b_att, W_out, b_out, out);
}

// round 8
// speedup vs baseline: 1.5615x; 1.5615x over previous
#include <cuda_runtime.h>
#include <math.h>
#include <stdint.h>

// ---------------- device scratch ----------------
__device__ __align__(16) float g_trel[500 * 100];
__device__ __align__(16) float g_tin[8192 * 500];
__device__ __align__(16) float g_xp[8192 * 1024];
__device__ __align__(16) float g_outseq[8192 * 256];

// ---------------- helpers ----------------
__device__ __forceinline__ unsigned smem_u32(const void* p) {
    return (unsigned)__cvta_generic_to_shared(p);
}
__device__ __forceinline__ void cpa16(unsigned dst, const void* src) {
    asm volatile("cp.async.cg.shared.global [%0], [%1], 16;\n" :: "r"(dst), "l"(src));
}
#define CPA_COMMIT() asm volatile("cp.async.commit_group;\n")
template <int N> __device__ __forceinline__ void cpa_wait() {
    asm volatile("cp.async.wait_group %0;\n" :: "n"(N));
}
#define FMA2(acc, h, w) \
    asm("fma.rn.f32x2 %0, %1, %2, %0;" : "+l"(acc) : "l"(h), "l"(w))
#define UNPACK2(lo, hi, src) \
    asm("mov.b64 {%0, %1}, %2;" : "=f"(lo), "=f"(hi) : "l"(src))
#define PACKF2(dst, a, b) \
    asm("mov.b64 %0, {%1, %2};" : "=l"(dst) : "f"(a), "f"(b))
#define CLUSTER_ARRIVE() asm volatile("barrier.cluster.arrive.aligned;" ::: "memory")
#define CLUSTER_WAIT()   asm volatile("barrier.cluster.wait.aligned;" ::: "memory")

__device__ __forceinline__ float fast_sigmoid(float x) {
    return __fdividef(1.f, 1.f + __expf(-x));
}
__device__ __forceinline__ float fast_tanh(float x) {
    float e = __expf(2.f * x);
    return 1.f - __fdividef(2.f, e + 1.f);
}

// ============================================================================
// K0: precompute tanh(rel_emb)
// ============================================================================
__global__ void k_tanh_rel(const float* __restrict__ rel) {
    int i = blockIdx.x * 256 + threadIdx.x;
    if (i < 500 * 100) g_trel[i] = tanhf(rel[i]);
}

// ============================================================================
// K1: graph attention. 512 CTAs x 512 threads, 16 tokens per CTA.
// ============================================================================
#define TOK_SW    0
#define TOK_SHT   20400
#define TOK_SRT   33456
#define TOK_SE    39856
#define TOK_SIDX  39888
#define TOK_SVAL  41424
#define TOK_SPART 41440
#define TOK_SMEM  ((41440 + 32 * 52) * 4)

__device__ __forceinline__ void tok_stage(float* sm, int buf, int it,
                                          const float* ent_emb) {
    const int* idx = (const int*)(sm + TOK_SIDX) + it * 96;
    float* sHT = sm + TOK_SHT + buf * 32 * 204;
    float* sRT = sm + TOK_SRT + buf * 32 * 100;
    for (int i = threadIdx.x; i < 2400; i += 512) {
        if (i < 1600) {
            int t = i / 50, j = i - t * 50;
            int ent = (j < 25) ? idx[t * 3] : idx[t * 3 + 1];
            int jj = (j < 25) ? j : (j - 25);
            int dstf = t * 204 + ((j < 25) ? (j * 4) : (100 + jj * 4));
            cpa16(smem_u32(sHT + dstf), ent_emb + (size_t)ent * 100 + jj * 4);
        } else {
            int r = i - 1600;
            int t = r / 25, j = r - t * 25;
            int rl = idx[t * 3 + 2];
            cpa16(smem_u32(sRT + t * 100 + j * 4), g_trel + rl * 100 + j * 4);
        }
    }
}

__global__ void __launch_bounds__(512, 1)
k_token(const int* __restrict__ inputs, const int* __restrict__ triples,
        const int* __restrict__ id2, const float* __restrict__ word_emb,
        const float* __restrict__ ent_emb, const float* __restrict__ W_ent)
{
    extern __shared__ float sm[];
    const int tid = threadIdx.x;
    const int tok0 = blockIdx.x * 16;

    for (int i = tid; i < 384; i += 512)
        cpa16(smem_u32(sm + TOK_SIDX) + i * 16, triples + (size_t)tok0 * 96 + i * 4);
    for (int i = tid; i < 5000; i += 512) {
        int d = i / 50, j = i - d * 50;
        cpa16(smem_u32(sm + TOK_SW + d * 204 + j * 4), W_ent + d * 200 + j * 4);
    }
    CPA_COMMIT();
    cpa_wait<0>();
    __syncthreads();

    {
        int it = tid >> 5, lane = tid & 31;
        int v = id2[(size_t)(tok0 + it) * 32 + lane];
        unsigned m = __ballot_sync(0xffffffffu, v != -1);
        if (lane == 0) ((int*)(sm + TOK_SVAL))[it] = (m != 0u);
    }

    tok_stage(sm, 0, 0, ent_emb);
    CPA_COMMIT();

    const int tt = tid & 7;
    const int dd = tid >> 3;

    for (int it = 0; it < 16; ++it) {
        const int buf = it & 1;
        if (it < 15) {
            tok_stage(sm, buf ^ 1, it + 1, ent_emb);
            CPA_COMMIT();
            cpa_wait<1>();
        } else {
            cpa_wait<0>();
        }
        __syncthreads();

        const float* sHT = sm + TOK_SHT + buf * 32 * 204;
        const float* sRT = sm + TOK_SRT + buf * 32 * 100;
        const int token = tok0 + it;
        const int widx = inputs[token];

        if (tid < 400) {
            const float* pa = sHT + tt * 204;
            const float* pb0 = sm + TOK_SW + dd * 204;
            const float* pb1 = sm + TOK_SW + (dd + 50) * 204;
            float acc[4][2];
            #pragma unroll
            for (int i = 0; i < 4; i++) { acc[i][0] = 0.f; acc[i][1] = 0.f; }

            #pragma unroll 2
            for (int j = 0; j < 50; ++j) {
                float4 b0 = *(const float4*)(pb0 + j * 4);
                float4 b1 = *(const float4*)(pb1 + j * 4);
                #pragma unroll
                for (int i = 0; i < 4; ++i) {
                    float4 a = *(const float4*)(pa + i * (8 * 204) + j * 4);
                    acc[i][0] = fmaf(a.x, b0.x, fmaf(a.y, b0.y, fmaf(a.z, b0.z, fmaf(a.w, b0.w, acc[i][0]))));
                    acc[i][1] = fmaf(a.x, b1.x, fmaf(a.y, b1.y, fmaf(a.z, b1.z, fmaf(a.w, b1.w, acc[i][1]))));
                }
            }
            #pragma unroll
            for (int i = 0; i < 4; ++i) {
                int t = tt + 8 * i;
                float c = fast_tanh(acc[i][0]) * sRT[t * 100 + dd]
                        + fast_tanh(acc[i][1]) * sRT[t * 100 + dd + 50];
                sm[TOK_SPART + t * 52 + dd] = c;
            }
        } else {
            // gemm-idle warps: copy word embedding concurrently (DRAM gather)
            const float2* wsrc = (const float2*)(word_emb + (size_t)widx * 300);
            float2* wdst = (float2*)(g_tin + (size_t)token * 500);
            for (int j = tid - 400; j < 150; j += 112) wdst[j] = wsrc[j];
        }
        __syncthreads();

        {
            int t = tid >> 4, l = tid & 15;
            float v = sm[TOK_SPART + t * 52 + l]
                    + sm[TOK_SPART + t * 52 + l + 16]
                    + sm[TOK_SPART + t * 52 + l + 32];
            if (l < 2) v += sm[TOK_SPART + t * 52 + l + 48];
            #pragma unroll
            for (int o = 8; o; o >>= 1) v += __shfl_xor_sync(0xffffffffu, v, o);
            if (l == 0) sm[TOK_SE + t] = v;
        }
        __syncthreads();

        if (tid < 32) {
            float v = sm[TOK_SE + tid];
            float m = v;
            #pragma unroll
            for (int o = 16; o; o >>= 1) m = fmaxf(m, __shfl_xor_sync(0xffffffffu, m, o));
            float e = __expf(v - m);
            float z = e;
            #pragma unroll
            for (int o = 16; o; o >>= 1) z += __shfl_xor_sync(0xffffffffu, z, o);
            sm[TOK_SE + tid] = e / z;
        }
        __syncthreads();

        if (tid < 200) {
            float ge = 0.f;
            #pragma unroll 8
            for (int t = 0; t < 32; ++t) ge += sm[TOK_SE + t] * sHT[t * 204 + tid];
            int valid = ((int*)(sm + TOK_SVAL))[it];
            g_tin[(size_t)token * 500 + 300 + tid] = valid ? ge : 0.f;
        }
        __syncthreads();
    }
}

// ============================================================================
// K2: g_xp[8192,1024] = g_tin[8192,500] @ w_ih^T + (b_ih + b_hh)
// 64x64x16 tiles, 4x4 thread tiles, 256 threads, register double-buffer.
// ============================================================================
__global__ void __launch_bounds__(256)
k_gemm_x(const float* __restrict__ wih, const float* __restrict__ bih,
         const float* __restrict__ bhh)
{
    __shared__ float As[16 * 68];
    __shared__ float Bs[16 * 68];
    const int tid = threadIdx.x;
    const int n0 = blockIdx.x * 64;
    const int m0 = blockIdx.y * 64;
    const int lm = tid >> 2;
    const int lk = (tid & 3) * 4;
    const int ty = tid >> 4;
    const int tx = tid & 15;

    float acc[4][4];
    #pragma unroll
    for (int i = 0; i < 4; i++)
        #pragma unroll
        for (int j = 0; j < 4; j++) acc[i][j] = 0.f;

    const float* arow = g_tin + (size_t)(m0 + lm) * 500;
    const float* brow = wih   + (size_t)(n0 + lm) * 500;

    float ar[4], br[4];
    #pragma unroll
    for (int j = 0; j < 4; ++j) {
        int k = lk + j;
        ar[j] = arow[k];
        br[j] = brow[k];
    }

    for (int kt = 0; kt < 32; ++kt) {
        #pragma unroll
        for (int j = 0; j < 4; ++j) {
            As[(lk + j) * 68 + lm] = ar[j];
            Bs[(lk + j) * 68 + lm] = br[j];
        }
        __syncthreads();

        if (kt < 31) {                       // prefetch next tile (hidden)
            int kb = (kt + 1) * 16;
            #pragma unroll
            for (int j = 0; j < 4; ++j) {
                int k = kb + lk + j;
                ar[j] = (k < 500) ? arow[k] : 0.f;
                br[j] = (k < 500) ? brow[k] : 0.f;
            }
        }

        #pragma unroll
        for (int k = 0; k < 16; ++k) {
            float4 a = *(const float4*)&As[k * 68 + ty * 4];
            float4 b = *(const float4*)&Bs[k * 68 + tx * 4];
            acc[0][0] += a.x*b.x; acc[0][1] += a.x*b.y; acc[0][2] += a.x*b.z; acc[0][3] += a.x*b.w;
            acc[1][0] += a.y*b.x; acc[1][1] += a.y*b.y; acc[1][2] += a.y*b.z; acc[1][3] += a.y*b.w;
            acc[2][0] += a.z*b.x; acc[2][1] += a.z*b.y; acc[2][2] += a.z*b.z; acc[2][3] += a.z*b.w;
            acc[3][0] += a.w*b.x; acc[3][1] += a.w*b.y; acc[3][2] += a.w*b.z; acc[3][3] += a.w*b.w;
        }
        __syncthreads();
    }
    #pragma unroll
    for (int j = 0; j < 4; ++j) {
        int n = n0 + tx * 4 + j;
        float bias = bih[n] + bhh[n];
        #pragma unroll
        for (int i = 0; i < 4; ++i)
            g_xp[(size_t)(m0 + ty * 4 + i) * 1024 + n] = acc[i][j] + bias;
    }
}

// ============================================================================
// K3: cluster LSTM (round-6 design). 16 clusters x 8 CTAs x 256 threads.
// Weights in regs (4 gates x 16 u64 k-pairs = 128 regs). h in smem swizzled;
// butterfly reduce; lanes ks<4 activate; DSMEM scalar stores; cluster.sync.
// ============================================================================
__global__ void __launch_bounds__(256, 1) __cluster_dims__(8, 1, 1)
k_lstm(const float* __restrict__ whh, const int* __restrict__ lengths)
{
    __shared__ __align__(16) float sH[2][4][256];   // [buf][batch][k swizzled]

    const int tid  = threadIdx.x;
    const int rank = blockIdx.x & 7;
    const int cid  = blockIdx.x >> 3;
    const int b0g  = cid * 4;

    const int hc_l = tid >> 3;          // 0..31
    const int ks   = tid & 7;           // k-slice
    const int k_g  = rank * 32 + hc_l;

    // ---- persistent packed weights: 4 gates x 32 k = 64 u64 = 128 regs ----
    unsigned long long w[4][16];
    #pragma unroll
    for (int g = 0; g < 4; ++g) {
        const float4* p = (const float4*)(whh + ((size_t)(g * 256 + k_g)) * 256 + ks * 32);
        #pragma unroll
        for (int j = 0; j < 8; ++j) {
            float4 v = __ldg(p + j);
            PACKF2(w[g][2*j],   v.x, v.y);
            PACKF2(w[g][2*j+1], v.z, v.w);
        }
    }

    for (int i = tid; i < 2 * 4 * 256; i += 256) (&sH[0][0][0])[i] = 0.f;

    const int ab = ks;                  // batch for activation lanes (ks<4)
    float cst = 0.f;
    int mylen = 0;
    if (ks < 4) mylen = lengths[b0g + ab];
    const int sw_idx = k_g ^ (rank << 2);

    __syncthreads();
    CLUSTER_ARRIVE(); CLUSTER_WAIT();

    int buf = 0;
    for (int s = 0; s < 128; ++s) {
        float xg0 = 0.f, xg1 = 0.f, xg2 = 0.f, xg3 = 0.f;
        if (ks < 4) {
            const float* xp = g_xp + ((size_t)((b0g + ab) * 128 + s)) * 1024 + k_g;
            xg0 = __ldg(xp);       xg1 = __ldg(xp + 256);
            xg2 = __ldg(xp + 512); xg3 = __ldg(xp + 768);
        }

        unsigned long long acc[4][4];
        #pragma unroll
        for (int g = 0; g < 4; ++g)
            #pragma unroll
            for (int b = 0; b < 4; ++b) acc[g][b] = 0ull;

        const float* hb = &sH[buf][0][0];
        #pragma unroll
        for (int i = 0; i < 8; ++i) {
            int off = (ks * 32 + i * 4) ^ (ks << 2);
            ulonglong2 x0 = *(const ulonglong2*)(hb + 0   + off);
            ulonglong2 x1 = *(const ulonglong2*)(hb + 256 + off);
            ulonglong2 x2 = *(const ulonglong2*)(hb + 512 + off);
            ulonglong2 x3 = *(const ulonglong2*)(hb + 768 + off);
            #pragma unroll
            for (int g = 0; g < 4; ++g) {
                FMA2(acc[g][0], x0.x, w[g][2*i]); FMA2(acc[g][0], x0.y, w[g][2*i+1]);
                FMA2(acc[g][1], x1.x, w[g][2*i]); FMA2(acc[g][1], x1.y, w[g][2*i+1]);
                FMA2(acc[g][2], x2.x, w[g][2*i]); FMA2(acc[g][2], x2.y, w[g][2*i+1]);
                FMA2(acc[g][3], x3.x, w[g][2*i]); FMA2(acc[g][3], x3.y, w[g][2*i+1]);
            }
        }

        float r[4][4];
        #pragma unroll
        for (int g = 0; g < 4; ++g)
            #pragma unroll
            for (int b = 0; b < 4; ++b) {
                float lo, hi;
                UNPACK2(lo, hi, acc[g][b]);
                r[g][b] = lo + hi;
            }
        #pragma unroll
        for (int o = 1; o < 8; o <<= 1)
            #pragma unroll
            for (int g = 0; g < 4; ++g)
                #pragma unroll
                for (int b = 0; b < 4; ++b)
                    r[g][b] += __shfl_xor_sync(0xffffffffu, r[g][b], o);

        if (ks < 4) {
            float gi = xg0 + r[0][ab];
            float gf = xg1 + r[1][ab];
            float gg = xg2 + r[2][ab];
            float go = xg3 + r[3][ab];
            float si = fast_sigmoid(gi);
            float sf = fast_sigmoid(gf);
            float so = fast_sigmoid(go);
            cst = sf * cst + si * fast_tanh(gg);
            float hv = so * fast_tanh(cst);
            g_outseq[((size_t)((b0g + ab) * 128 + s)) * 256 + k_g] =
                (s < mylen) ? hv : 0.f;
            unsigned laddr = smem_u32(&sH[buf ^ 1][ab][sw_idx]);
            #pragma unroll
            for (int rr = 0; rr < 8; ++rr) {
                unsigned raddr;
                asm("mapa.shared::cluster.u32 %0, %1, %2;" : "=r"(raddr) : "r"(laddr), "r"(rr));
                asm volatile("st.shared::cluster.f32 [%0], %1;" :: "r"(raddr), "f"(hv));
            }
        }
        CLUSTER_ARRIVE();
        CLUSTER_WAIT();
        buf ^= 1;
    }
}

// ============================================================================
// K4: attention pool + classifier. out = [ log_probs (64*3) | p (64*128) ]
// ============================================================================
__global__ void __launch_bounds__(256)
k_final(const float* __restrict__ W_att, const float* __restrict__ b_att,
        const float* __restrict__ W_out, const float* __restrict__ b_out,
        float* __restrict__ out)
{
    __shared__ float sLog[128];
    __shared__ float sP[128];
    __shared__ float sEnc[256];
    __shared__ float sZ[3];
    const int tid = threadIdx.x;
    const int b = blockIdx.x;

    if (tid < 128) {
        const float* o = g_outseq + (size_t)(b * 128 + tid) * 256;
        float a = 0.f;
        for (int h = 0; h < 256; ++h) a += o[h] * W_att[h];
        sLog[tid] = a + b_att[0];
    }
    __syncthreads();

    if (tid < 32) {                       // warp-parallel masked softmax
        float lv[4], mk[4];
        #pragma unroll
        for (int i = 0; i < 4; ++i) {
            float x = sLog[tid + 32 * i];
            mk[i] = (x != 0.f) ? 1.f : 0.f;
            lv[i] = x * mk[i];
        }
        float mx = fmaxf(fmaxf(lv[0], lv[1]), fmaxf(lv[2], lv[3]));
        #pragma unroll
        for (int o = 16; o; o >>= 1) mx = fmaxf(mx, __shfl_xor_sync(0xffffffffu, mx, o));
        float e[4], den = 0.f;
        #pragma unroll
        for (int i = 0; i < 4; ++i) { e[i] = __expf(lv[i] - mx); den += e[i]; }
        #pragma unroll
        for (int o = 16; o; o >>= 1) den += __shfl_xor_sync(0xffffffffu, den, o);
        float pv[4], s2 = 0.f;
        #pragma unroll
        for (int i = 0; i < 4; ++i) { pv[i] = e[i] / den * mk[i]; s2 += pv[i]; }
        #pragma unroll
        for (int o = 16; o; o >>= 1) s2 += __shfl_xor_sync(0xffffffffu, s2, o);
        float inv = 1.f / (s2 + 1e-13f);
        #pragma unroll
        for (int i = 0; i < 4; ++i) sP[tid + 32 * i] = pv[i] * inv;
    }
    __syncthreads();

    {
        float a = 0.f;
        const float* base = g_outseq + (size_t)b * 128 * 256 + tid;
        for (int s = 0; s < 128; ++s) a += sP[s] * base[s * 256];
        sEnc[tid] = a;
    }
    __syncthreads();

    if (tid < 3) {
        float z = b_out[tid];
        const float* wv = W_out + tid * 256;
        for (int h = 0; h < 256; ++h) z += sEnc[h] * wv[h];
        sZ[tid] = z;
    }
    __syncthreads();
    if (tid < 3) {
        float mx = fmaxf(sZ[0], fmaxf(sZ[1], sZ[2]));
        float lse = mx + logf(expf(sZ[0] - mx) + expf(sZ[1] - mx) + expf(sZ[2] - mx));
        out[b * 3 + tid] = sZ[tid] - lse;
    }
    if (tid < 128) out[192 + b * 128 + tid] = sP[tid];
}

// ============================================================================
extern "C" void kernel_launch(void* const* d_in, const int* in_sizes, int n_in,
                              void* d_out, int out_size)
{
    const int*   inputs   = (const int*)d_in[0];
    const int*   triples  = (const int*)d_in[1];
    const int*   lengths  = (const int*)d_in[2];
    const int*   id2      = (const int*)d_in[3];
    const float* word_emb = (const float*)d_in[4];
    const float* ent_emb  = (const float*)d_in[5];
    const float* rel_emb  = (const float*)d_in[6];
    const float* W_ent    = (const float*)d_in[7];
    const float* w_ih     = (const float*)d_in[8];
    const float* w_hh     = (const float*)d_in[9];
    const float* b_ih     = (const float*)d_in[10];
    const float* b_hh     = (const float*)d_in[11];
    const float* W_att    = (const float*)d_in[12];
    const float* b_att    = (const float*)d_in[13];
    const float* W_out    = (const float*)d_in[14];
    const float* b_out    = (const float*)d_in[15];
    float* out = (float*)d_out;

    cudaFuncSetAttribute(k_token, cudaFuncAttributeMaxDynamicSharedMemorySize, TOK_SMEM);

    k_tanh_rel<<<(50000 + 255) / 256, 256>>>(rel_emb);
    k_token<<<512, 512, TOK_SMEM>>>(inputs, triples, id2, word_emb, ent_emb, W_ent);
    dim3 g2(16, 128);
    k_gemm_x<<<g2, 256>>>(w_ih, b_ih, b_hh);
    k_lstm<<<128, 256>>>(w_hh, lengths);
    k_final<<<64, 256>>>(W_att, b_att, W_out, b_out, out);
}